// round 16
// baseline (speedup 1.0000x reference)
#include <cuda_runtime.h>
#include <cuda_bf16.h>
#include <cstdint>
#include <cstddef>

#define B_  256
#define T_  2048
#define H_  128
#define G4_ 512                 // 4*H
#define M_  (B_ * T_)           // 524288

// Scratch (device globals — no cudaMalloc allowed)
__device__ float g_xp[(size_t)M_ * G4_];   // x @ W_ih^T + b_ih + b_hh   (1 GiB)
__device__ float g_hs[(size_t)M_ * H_];    // h_states [B][T][H]         (256 MiB)
__device__ uint2 g_whi[512 * 32];          // W_ih hi-bf16, [512 rows][32 uint2]
__device__ uint2 g_wlo[512 * 32];          // W_ih lo-bf16

// ===========================================================================
// Helpers
// ===========================================================================
__device__ __forceinline__ uint32_t smem_u32(const void* p) {
    uint32_t a;
    asm("{ .reg .u64 t; cvta.to.shared.u64 t, %1; cvt.u32.u64 %0, t; }"
        : "=r"(a) : "l"(p));
    return a;
}

__device__ __forceinline__ unsigned long long fma2(unsigned long long a,
                                                   unsigned long long b,
                                                   unsigned long long c) {
    unsigned long long d;
    asm("fma.rn.f32x2 %0, %1, %2, %3;" : "=l"(d) : "l"(a), "l"(b), "l"(c));
    return d;
}
__device__ __forceinline__ float sum2(unsigned long long v) {
    float lo, hi;
    asm("mov.b64 {%0, %1}, %2;" : "=f"(lo), "=f"(hi) : "l"(v));
    return lo + hi;
}

__device__ __forceinline__ void ldsm_x4(uint32_t* r, uint32_t addr) {
    asm volatile("ldmatrix.sync.aligned.m8n8.x4.shared.b16 {%0,%1,%2,%3}, [%4];"
                 : "=r"(r[0]), "=r"(r[1]), "=r"(r[2]), "=r"(r[3]) : "r"(addr));
}

__device__ __forceinline__ void mma16816(float* c, const uint32_t* a,
                                         uint32_t b0, uint32_t b1) {
    asm volatile(
        "mma.sync.aligned.m16n8k16.row.col.f32.bf16.bf16.f32 "
        "{%0,%1,%2,%3}, {%4,%5,%6,%7}, {%8,%9}, {%0,%1,%2,%3};"
        : "+f"(c[0]), "+f"(c[1]), "+f"(c[2]), "+f"(c[3])
        : "r"(a[0]), "r"(a[1]), "r"(a[2]), "r"(a[3]), "r"(b0), "r"(b1));
}

// fp32 -> (hi, lo) bf16 pairs packed as u32
__device__ __forceinline__ void split2(float a, float b, uint32_t& hi, uint32_t& lo) {
    __nv_bfloat16 ha = __float2bfloat16_rn(a);
    __nv_bfloat16 hb = __float2bfloat16_rn(b);
    float ra = a - __bfloat162float(ha);
    float rb = b - __bfloat162float(hb);
    __nv_bfloat16 la = __float2bfloat16_rn(ra);
    __nv_bfloat16 lb = __float2bfloat16_rn(rb);
    __nv_bfloat162 hp = __halves2bfloat162(ha, hb);
    __nv_bfloat162 lp = __halves2bfloat162(la, lb);
    hi = *reinterpret_cast<uint32_t*>(&hp);
    lo = *reinterpret_cast<uint32_t*>(&lp);
}

// ===========================================================================
// Kernel 0: one-shot split of W_ih into bf16 hi/lo (runs once, ~5us).
// ===========================================================================
__global__ __launch_bounds__(256) void wsplit_kernel(const float* __restrict__ Wih)
{
    int idx = blockIdx.x * 256 + threadIdx.x;   // 0..16383
    float4 v = reinterpret_cast<const float4*>(Wih)[idx];
    uint2 hi, lo;
    split2(v.x, v.y, hi.x, lo.x);
    split2(v.z, v.w, hi.y, lo.y);
    g_whi[idx] = hi;
    g_wlo[idx] = lo;
}

// ===========================================================================
// Kernel 1: x_proj via mma.sync bf16 split-precision GEMM (R14 config).
// CTA: 128 M-rows; N=512 in 8 chunks of 64; K=128 smem-resident.
// B path loads pre-split bf16 (no per-CTA conversion math).
// ===========================================================================
#define XS_AHI  0
#define XS_ALO  32768
#define XS_BHI  65536
#define XS_BLO  81920
#define XS_BIAS 98304
#define XS_SIZE 100352

__global__ __launch_bounds__(256) void xproj_mma_kernel(
    const float* __restrict__ x,
    const float* __restrict__ bih, const float* __restrict__ bhh)
{
    extern __shared__ __align__(128) char smem[];
    const uint32_t sb = smem_u32(smem);
    const int tid  = threadIdx.x;
    const int wid  = tid >> 5;
    const int lane = tid & 31;
    const int m0   = blockIdx.x * 128;

    float* s_bias = reinterpret_cast<float*>(smem + XS_BIAS);
    s_bias[tid]       = bih[tid]       + bhh[tid];
    s_bias[tid + 256] = bih[tid + 256] + bhh[tid + 256];

    // ---- load + split A (x tile: 128 rows x 128 k) ----
    const float4* x4 = reinterpret_cast<const float4*>(x);
    #pragma unroll
    for (int it = 0; it < 16; it++) {
        int idx = tid + it * 256;
        int r   = idx >> 5;
        int k4  = idx & 31;
        float4 v = x4[(size_t)(m0 + r) * 32 + k4];
        uint2 hi, lo;
        split2(v.x, v.y, hi.x, lo.x);
        split2(v.z, v.w, hi.y, lo.y);
        uint32_t ch = (uint32_t)(k4 >> 1) ^ (uint32_t)(r & 7);
        uint32_t off = (uint32_t)r * 256u + ch * 16u + (uint32_t)(k4 & 1) * 8u;
        *reinterpret_cast<uint2*>(smem + XS_AHI + off) = hi;
        *reinterpret_cast<uint2*>(smem + XS_ALO + off) = lo;
    }

    const int wm = wid & 3;
    const int wn = wid >> 2;

    const int a_row  = wm * 32 + (lane & 15);
    const int a_koff = lane >> 4;
    const int b_row  = ((lane >> 4) << 3) + (lane & 7);
    const int b_koff = (lane >> 3) & 1;

    // prefetch chunk 0 of pre-split B into regs
    uint2 phi[8], plo[8];
    #pragma unroll
    for (int it = 0; it < 8; it++) {
        int idx = tid + it * 256;
        phi[it] = g_whi[idx];
        plo[it] = g_wlo[idx];
    }

    for (int nc = 0; nc < 8; nc++) {
        const int n0g = nc * 64;

        // ---- store prefetched B chunk (swizzled; no conversion math) ----
        #pragma unroll
        for (int it = 0; it < 8; it++) {
            int idx = tid + it * 256;
            int r   = idx >> 5;
            int k4  = idx & 31;
            uint32_t ch = (uint32_t)(k4 >> 1) ^ (uint32_t)(r & 7);
            uint32_t off = (uint32_t)r * 256u + ch * 16u + (uint32_t)(k4 & 1) * 8u;
            *reinterpret_cast<uint2*>(smem + XS_BHI + off) = phi[it];
            *reinterpret_cast<uint2*>(smem + XS_BLO + off) = plo[it];
        }
        __syncthreads();

        // ---- prefetch next B chunk ----
        if (nc < 7) {
            #pragma unroll
            for (int it = 0; it < 8; it++) {
                int idx = (nc + 1) * 2048 + tid + it * 256;
                phi[it] = g_whi[idx];
                plo[it] = g_wlo[idx];
            }
        }

        float acc[2][4][4];
        #pragma unroll
        for (int mi = 0; mi < 2; mi++)
            #pragma unroll
            for (int ni = 0; ni < 4; ni++)
                #pragma unroll
                for (int q = 0; q < 4; q++) acc[mi][ni][q] = 0.0f;

        #pragma unroll
        for (int ks = 0; ks < 8; ks++) {
            uint32_t ahi[2][4], alo[2][4];
            #pragma unroll
            for (int mi = 0; mi < 2; mi++) {
                int r = a_row + mi * 16;
                uint32_t ch = (uint32_t)(ks * 2 + a_koff) ^ (uint32_t)(r & 7);
                uint32_t ad = sb + (uint32_t)r * 256u + ch * 16u;
                ldsm_x4(ahi[mi], ad + XS_AHI);
                ldsm_x4(alo[mi], ad + XS_ALO);
            }
            uint32_t bhi[2][4], blo[2][4];
            #pragma unroll
            for (int p = 0; p < 2; p++) {
                int r = wn * 32 + p * 16 + b_row;
                uint32_t ch = (uint32_t)(ks * 2 + b_koff) ^ (uint32_t)(r & 7);
                uint32_t ad = sb + (uint32_t)r * 256u + ch * 16u;
                ldsm_x4(bhi[p], ad + XS_BHI);
                ldsm_x4(blo[p], ad + XS_BLO);
            }
            #pragma unroll
            for (int mi = 0; mi < 2; mi++)
                #pragma unroll
                for (int ni = 0; ni < 4; ni++) {
                    int p = ni >> 1, q = ni & 1;
                    mma16816(acc[mi][ni], ahi[mi], bhi[p][q * 2], bhi[p][q * 2 + 1]);
                    mma16816(acc[mi][ni], ahi[mi], blo[p][q * 2], blo[p][q * 2 + 1]);
                    mma16816(acc[mi][ni], alo[mi], bhi[p][q * 2], bhi[p][q * 2 + 1]);
                }
        }

        // ---- epilogue ----
        #pragma unroll
        for (int mi = 0; mi < 2; mi++) {
            #pragma unroll
            for (int ni = 0; ni < 4; ni++) {
                int ncol = n0g + wn * 32 + ni * 8 + (lane & 3) * 2;
                int mrow = m0 + wm * 32 + mi * 16 + (lane >> 2);
                float bx = s_bias[ncol], by = s_bias[ncol + 1];
                float2 v0 = make_float2(acc[mi][ni][0] + bx, acc[mi][ni][1] + by);
                float2 v1 = make_float2(acc[mi][ni][2] + bx, acc[mi][ni][3] + by);
                *reinterpret_cast<float2*>(g_xp + (size_t)mrow * G4_ + ncol) = v0;
                *reinterpret_cast<float2*>(g_xp + (size_t)(mrow + 8) * G4_ + ncol) = v1;
            }
        }
        __syncthreads();
    }
}

// ===========================================================================
// Kernel 2: persistent LSTM scan — EXACT R12 config (frozen optimum, 96% of
// the fp32 FMA floor). tanh.approx activations.
// 128 CTAs x 2 batch rows x 512 threads.
// ===========================================================================
__device__ __forceinline__ float tanh_fast(float x) {
    float y;
    asm("tanh.approx.f32 %0, %1;" : "=f"(y) : "f"(x));
    return y;
}
__device__ __forceinline__ float sigmoid_fast(float x) {
    return fmaf(tanh_fast(0.5f * x), 0.5f, 0.5f);
}

#define LS_SMEM ((256 + 2048 + 32768) * 4)   // sh_h + gbuf + Wst = 140288 B

__global__ __launch_bounds__(512, 1) void lstm_kernel(const float* __restrict__ Whh)
{
    extern __shared__ float smem_l[];
    float*  sh_h = smem_l;                 // [2][128]
    float*  gbuf = smem_l + 256;           // 2048 gate partials
    float4* Wst  = reinterpret_cast<float4*>(smem_l + 256 + 2048); // [32 k4][256 r]

    const int tid = threadIdx.x;
    const int hb  = tid >> 8;
    const int r   = tid & 255;
    const int b0  = blockIdx.x * 2;

    const ulonglong2* Wll = reinterpret_cast<const ulonglong2*>(Whh);
    const float4*     W4  = reinterpret_cast<const float4*>(Whh);

    unsigned long long wr[32];
    #pragma unroll
    for (int i = 0; i < 16; i++) {
        ulonglong2 v = Wll[(size_t)r * 32 + (hb << 4) + i];
        wr[2 * i]     = v.x;
        wr[2 * i + 1] = v.y;
    }
    #pragma unroll
    for (int i = 0; i < 16; i++) {
        int idx = tid + (i << 9);
        int k4 = idx >> 8, rr = idx & 255;
        Wst[k4 * 256 + rr] = W4[(size_t)(256 + rr) * 32 + k4];
    }

    if (tid < 256) sh_h[tid] = 0.0f;
    float c_reg = 0.0f;

    const bool cb = (tid < 256);
    const int  b  = (tid >> 7) & 1;
    const int  j  = tid & 127;

    const float* my_xp = g_xp + (size_t)(b0 + b) * T_ * G4_;
    float*       my_hs = g_hs + (size_t)(b0 + b) * T_ * H_;

    const char* sh0 = (const char*)sh_h + (hb << 8);
    const float4* Wmy = Wst + (hb << 4) * 256 + r;

    __syncthreads();

    for (int t = 0; t < T_; t++) {
        float xpi = 0.f, xpf = 0.f, xpg = 0.f, xpo = 0.f;
        if (cb) {
            const float* xpt = my_xp + (size_t)t * G4_;
            xpi = __ldg(xpt + j);
            xpf = __ldg(xpt + 128 + j);
            xpg = __ldg(xpt + 256 + j);
            xpo = __ldg(xpt + 384 + j);
        }

        unsigned long long aa0 = 0ull, aa1 = 0ull;
        unsigned long long qq0 = 0ull, qq1 = 0ull;
        #pragma unroll
        for (int kk = 0; kk < 16; kk++) {
            ulonglong2 h0 = *reinterpret_cast<const ulonglong2*>(sh0 + kk * 16);
            ulonglong2 h1 = *reinterpret_cast<const ulonglong2*>(sh0 + 512 + kk * 16);
            ulonglong2 ws = *reinterpret_cast<const ulonglong2*>(Wmy + kk * 256);
            aa0 = fma2(wr[2 * kk],     h0.x, aa0);
            aa0 = fma2(wr[2 * kk + 1], h0.y, aa0);
            aa1 = fma2(wr[2 * kk],     h1.x, aa1);
            aa1 = fma2(wr[2 * kk + 1], h1.y, aa1);
            qq0 = fma2(ws.x, h0.x, qq0);
            qq0 = fma2(ws.y, h0.y, qq0);
            qq1 = fma2(ws.x, h1.x, qq1);
            qq1 = fma2(ws.y, h1.y, qq1);
        }
        gbuf[(hb << 9) + r]               = sum2(aa0);
        gbuf[(hb << 9) + 256 + r]         = sum2(aa1);
        gbuf[1024 + (hb << 9) + r]        = sum2(qq0);
        gbuf[1024 + (hb << 9) + 256 + r]  = sum2(qq1);
        __syncthreads();

        if (cb) {
            float gi = gbuf[(b << 8) + j]              + gbuf[512 + (b << 8) + j]              + xpi;
            float gf = gbuf[(b << 8) + 128 + j]        + gbuf[512 + (b << 8) + 128 + j]        + xpf;
            float gg = gbuf[1024 + (b << 8) + j]       + gbuf[1536 + (b << 8) + j]             + xpg;
            float go = gbuf[1024 + (b << 8) + 128 + j] + gbuf[1536 + (b << 8) + 128 + j]       + xpo;

            float si = sigmoid_fast(gi);
            float sf = sigmoid_fast(gf);
            float so = sigmoid_fast(go);
            float tg = tanh_fast(gg);

            c_reg = fmaf(sf, c_reg, si * tg);
            float hn = so * tanh_fast(c_reg);

            sh_h[(b << 7) + j]        = hn;
            my_hs[(size_t)t * H_ + j] = hn;
        }
        __syncthreads();
    }
}

// ===========================================================================
// Kernel 3: attention pooling — fused online softmax, tile shrunk to 64
// timesteps (static smem ~35 KB) so up to 6 CTAs/SM co-reside: one wave,
// cross-CTA DRAM overlap. One CTA per batch row, 32 tiles.
// ===========================================================================
#define AT_TILE 64

__global__ __launch_bounds__(256) void attn_kernel(float* __restrict__ out)
{
    __shared__ float h_sm[AT_TILE * H_];   // 32 KB tile
    __shared__ float s_sc[AT_TILE];
    __shared__ float red[8];
    __shared__ float redA[256];
    __shared__ float redL[256];

    const int b    = blockIdx.x;
    const int tid  = threadIdx.x;
    const int lane = tid & 31;
    const int warp = tid >> 5;
    const int j    = tid & 127;
    const int tp   = tid >> 7;

    const float4* hs4 = reinterpret_cast<const float4*>(g_hs + (size_t)b * T_ * H_);
    float4* h_sm4 = reinterpret_cast<float4*>(h_sm);

    const float4 hl = hs4[(size_t)(T_ - 1) * 32 + lane];

    float m_run = -3.0e38f;
    float accj  = 0.0f;
    float lpart = 0.0f;

    for (int tile = 0; tile < T_ / AT_TILE; tile++) {
        const int t0 = tile * AT_TILE;

        // ---- load tile: 64 t x 128 j (2048 float4s) ----
        #pragma unroll
        for (int i = 0; i < 8; i++) {
            int idx = tid + i * 256;
            h_sm4[idx] = hs4[(size_t)(t0 + (idx >> 5)) * 32 + (idx & 31)];
        }
        __syncthreads();

        // ---- scores for this tile ----
        float lmax = -3.0e38f;
        #pragma unroll
        for (int i = 0; i < 8; i++) {
            int t = warp + 8 * i;
            float4 hv = h_sm4[t * 32 + lane];
            float d = fmaf(hv.x, hl.x, fmaf(hv.y, hl.y, fmaf(hv.z, hl.z, hv.w * hl.w)));
            #pragma unroll
            for (int s = 16; s > 0; s >>= 1) d += __shfl_xor_sync(0xffffffffu, d, s);
            if (lane == 0) s_sc[t] = d;
            lmax = fmaxf(lmax, d);
        }
        if (lane == 0) red[warp] = lmax;
        __syncthreads();

        float tmax = red[0];
        #pragma unroll
        for (int w = 1; w < 8; w++) tmax = fmaxf(tmax, red[w]);
        const float new_m = fmaxf(m_run, tmax);
        const float fac   = __expf(m_run - new_m);
        accj  *= fac;
        lpart *= fac;
        m_run  = new_m;

        if (tid < AT_TILE) s_sc[tid] = __expf(s_sc[tid] - new_m);
        __syncthreads();

        #pragma unroll 4
        for (int i = 0; i < AT_TILE / 2; i++) {
            int t = tp + 2 * i;
            float w = s_sc[t];
            accj = fmaf(w, h_sm[t * H_ + j], accj);
            lpart += w;
        }
        __syncthreads();
    }

    redA[tid] = accj;
    redL[tid] = lpart;
    __syncthreads();
    if (tid < 128) {
        float a = redA[tid] + redA[tid + 128];
        float l = redL[tid] + redL[tid + 128];
        out[b * H_ + tid] = a * __fdividef(1.0f, l);
    }
}

// ===========================================================================
extern "C" void kernel_launch(void* const* d_in, const int* in_sizes, int n_in,
                              void* d_out, int out_size)
{
    (void)in_sizes; (void)n_in; (void)out_size;
    const float* x   = (const float*)d_in[0];
    const float* Wih = (const float*)d_in[1];
    const float* Whh = (const float*)d_in[2];
    const float* bih = (const float*)d_in[3];
    const float* bhh = (const float*)d_in[4];
    float* out = (float*)d_out;

    cudaFuncSetAttribute(xproj_mma_kernel, cudaFuncAttributeMaxDynamicSharedMemorySize, XS_SIZE);
    cudaFuncSetAttribute(lstm_kernel,      cudaFuncAttributeMaxDynamicSharedMemorySize, LS_SMEM);

    wsplit_kernel<<<64, 256>>>(Wih);
    xproj_mma_kernel<<<M_ / 128, 256, XS_SIZE>>>(x, bih, bhh);
    lstm_kernel<<<B_ / 2, 512, LS_SMEM>>>(Whh);
    attn_kernel<<<B_, 256>>>(out);
}

// round 17
// speedup vs baseline: 1.0108x; 1.0108x over previous
#include <cuda_runtime.h>
#include <cuda_bf16.h>
#include <cstdint>
#include <cstddef>

#define B_  256
#define T_  2048
#define H_  128
#define G4_ 512                 // 4*H
#define M_  (B_ * T_)           // 524288

// Scratch (device globals — no cudaMalloc allowed)
__device__ float g_xp[(size_t)M_ * G4_];   // x @ W_ih^T + b_ih + b_hh   (1 GiB)
__device__ float g_hs[(size_t)M_ * H_];    // h_states [B][T][H]         (256 MiB)
__device__ uint2 g_whi[512 * 32];          // W_ih hi-bf16, [512 rows][32 uint2]
__device__ uint2 g_wlo[512 * 32];          // W_ih lo-bf16

// ===========================================================================
// Helpers
// ===========================================================================
__device__ __forceinline__ uint32_t smem_u32(const void* p) {
    uint32_t a;
    asm("{ .reg .u64 t; cvta.to.shared.u64 t, %1; cvt.u32.u64 %0, t; }"
        : "=r"(a) : "l"(p));
    return a;
}

__device__ __forceinline__ unsigned long long fma2(unsigned long long a,
                                                   unsigned long long b,
                                                   unsigned long long c) {
    unsigned long long d;
    asm("fma.rn.f32x2 %0, %1, %2, %3;" : "=l"(d) : "l"(a), "l"(b), "l"(c));
    return d;
}
__device__ __forceinline__ float sum2(unsigned long long v) {
    float lo, hi;
    asm("mov.b64 {%0, %1}, %2;" : "=f"(lo), "=f"(hi) : "l"(v));
    return lo + hi;
}

__device__ __forceinline__ void ldsm_x4(uint32_t* r, uint32_t addr) {
    asm volatile("ldmatrix.sync.aligned.m8n8.x4.shared.b16 {%0,%1,%2,%3}, [%4];"
                 : "=r"(r[0]), "=r"(r[1]), "=r"(r[2]), "=r"(r[3]) : "r"(addr));
}

__device__ __forceinline__ void mma16816(float* c, const uint32_t* a,
                                         uint32_t b0, uint32_t b1) {
    asm volatile(
        "mma.sync.aligned.m16n8k16.row.col.f32.bf16.bf16.f32 "
        "{%0,%1,%2,%3}, {%4,%5,%6,%7}, {%8,%9}, {%0,%1,%2,%3};"
        : "+f"(c[0]), "+f"(c[1]), "+f"(c[2]), "+f"(c[3])
        : "r"(a[0]), "r"(a[1]), "r"(a[2]), "r"(a[3]), "r"(b0), "r"(b1));
}

// fp32 -> (hi, lo) bf16 pairs packed as u32
__device__ __forceinline__ void split2(float a, float b, uint32_t& hi, uint32_t& lo) {
    __nv_bfloat16 ha = __float2bfloat16_rn(a);
    __nv_bfloat16 hb = __float2bfloat16_rn(b);
    float ra = a - __bfloat162float(ha);
    float rb = b - __bfloat162float(hb);
    __nv_bfloat16 la = __float2bfloat16_rn(ra);
    __nv_bfloat16 lb = __float2bfloat16_rn(rb);
    __nv_bfloat162 hp = __halves2bfloat162(ha, hb);
    __nv_bfloat162 lp = __halves2bfloat162(la, lb);
    hi = *reinterpret_cast<uint32_t*>(&hp);
    lo = *reinterpret_cast<uint32_t*>(&lp);
}

// ===========================================================================
// Kernel 0: one-shot split of W_ih into bf16 hi/lo (runs once, ~5us).
// ===========================================================================
__global__ __launch_bounds__(256) void wsplit_kernel(const float* __restrict__ Wih)
{
    int idx = blockIdx.x * 256 + threadIdx.x;   // 0..16383
    float4 v = reinterpret_cast<const float4*>(Wih)[idx];
    uint2 hi, lo;
    split2(v.x, v.y, hi.x, lo.x);
    split2(v.z, v.w, hi.y, lo.y);
    g_whi[idx] = hi;
    g_wlo[idx] = lo;
}

// ===========================================================================
// Kernel 1: x_proj via mma.sync bf16 split-precision GEMM (R14 config —
// best measured ~555us). CTA: 128 M-rows; N=512 in 8 chunks of 64; K=128
// smem-resident. B path loads pre-split bf16 (no per-CTA conversion math).
// ===========================================================================
#define XS_AHI  0
#define XS_ALO  32768
#define XS_BHI  65536
#define XS_BLO  81920
#define XS_BIAS 98304
#define XS_SIZE 100352

__global__ __launch_bounds__(256) void xproj_mma_kernel(
    const float* __restrict__ x,
    const float* __restrict__ bih, const float* __restrict__ bhh)
{
    extern __shared__ __align__(128) char smem[];
    const uint32_t sb = smem_u32(smem);
    const int tid  = threadIdx.x;
    const int wid  = tid >> 5;
    const int lane = tid & 31;
    const int m0   = blockIdx.x * 128;

    float* s_bias = reinterpret_cast<float*>(smem + XS_BIAS);
    s_bias[tid]       = bih[tid]       + bhh[tid];
    s_bias[tid + 256] = bih[tid + 256] + bhh[tid + 256];

    // ---- load + split A (x tile: 128 rows x 128 k) ----
    const float4* x4 = reinterpret_cast<const float4*>(x);
    #pragma unroll
    for (int it = 0; it < 16; it++) {
        int idx = tid + it * 256;
        int r   = idx >> 5;
        int k4  = idx & 31;
        float4 v = x4[(size_t)(m0 + r) * 32 + k4];
        uint2 hi, lo;
        split2(v.x, v.y, hi.x, lo.x);
        split2(v.z, v.w, hi.y, lo.y);
        uint32_t ch = (uint32_t)(k4 >> 1) ^ (uint32_t)(r & 7);
        uint32_t off = (uint32_t)r * 256u + ch * 16u + (uint32_t)(k4 & 1) * 8u;
        *reinterpret_cast<uint2*>(smem + XS_AHI + off) = hi;
        *reinterpret_cast<uint2*>(smem + XS_ALO + off) = lo;
    }

    const int wm = wid & 3;
    const int wn = wid >> 2;

    const int a_row  = wm * 32 + (lane & 15);
    const int a_koff = lane >> 4;
    const int b_row  = ((lane >> 4) << 3) + (lane & 7);
    const int b_koff = (lane >> 3) & 1;

    // prefetch chunk 0 of pre-split B into regs
    uint2 phi[8], plo[8];
    #pragma unroll
    for (int it = 0; it < 8; it++) {
        int idx = tid + it * 256;
        phi[it] = g_whi[idx];
        plo[it] = g_wlo[idx];
    }

    for (int nc = 0; nc < 8; nc++) {
        const int n0g = nc * 64;

        // ---- store prefetched B chunk (swizzled; no conversion math) ----
        #pragma unroll
        for (int it = 0; it < 8; it++) {
            int idx = tid + it * 256;
            int r   = idx >> 5;
            int k4  = idx & 31;
            uint32_t ch = (uint32_t)(k4 >> 1) ^ (uint32_t)(r & 7);
            uint32_t off = (uint32_t)r * 256u + ch * 16u + (uint32_t)(k4 & 1) * 8u;
            *reinterpret_cast<uint2*>(smem + XS_BHI + off) = phi[it];
            *reinterpret_cast<uint2*>(smem + XS_BLO + off) = plo[it];
        }
        __syncthreads();

        // ---- prefetch next B chunk ----
        if (nc < 7) {
            #pragma unroll
            for (int it = 0; it < 8; it++) {
                int idx = (nc + 1) * 2048 + tid + it * 256;
                phi[it] = g_whi[idx];
                plo[it] = g_wlo[idx];
            }
        }

        float acc[2][4][4];
        #pragma unroll
        for (int mi = 0; mi < 2; mi++)
            #pragma unroll
            for (int ni = 0; ni < 4; ni++)
                #pragma unroll
                for (int q = 0; q < 4; q++) acc[mi][ni][q] = 0.0f;

        #pragma unroll
        for (int ks = 0; ks < 8; ks++) {
            uint32_t ahi[2][4], alo[2][4];
            #pragma unroll
            for (int mi = 0; mi < 2; mi++) {
                int r = a_row + mi * 16;
                uint32_t ch = (uint32_t)(ks * 2 + a_koff) ^ (uint32_t)(r & 7);
                uint32_t ad = sb + (uint32_t)r * 256u + ch * 16u;
                ldsm_x4(ahi[mi], ad + XS_AHI);
                ldsm_x4(alo[mi], ad + XS_ALO);
            }
            uint32_t bhi[2][4], blo[2][4];
            #pragma unroll
            for (int p = 0; p < 2; p++) {
                int r = wn * 32 + p * 16 + b_row;
                uint32_t ch = (uint32_t)(ks * 2 + b_koff) ^ (uint32_t)(r & 7);
                uint32_t ad = sb + (uint32_t)r * 256u + ch * 16u;
                ldsm_x4(bhi[p], ad + XS_BHI);
                ldsm_x4(blo[p], ad + XS_BLO);
            }
            #pragma unroll
            for (int mi = 0; mi < 2; mi++)
                #pragma unroll
                for (int ni = 0; ni < 4; ni++) {
                    int p = ni >> 1, q = ni & 1;
                    mma16816(acc[mi][ni], ahi[mi], bhi[p][q * 2], bhi[p][q * 2 + 1]);
                    mma16816(acc[mi][ni], ahi[mi], blo[p][q * 2], blo[p][q * 2 + 1]);
                    mma16816(acc[mi][ni], alo[mi], bhi[p][q * 2], bhi[p][q * 2 + 1]);
                }
        }

        // ---- epilogue ----
        #pragma unroll
        for (int mi = 0; mi < 2; mi++) {
            #pragma unroll
            for (int ni = 0; ni < 4; ni++) {
                int ncol = n0g + wn * 32 + ni * 8 + (lane & 3) * 2;
                int mrow = m0 + wm * 32 + mi * 16 + (lane >> 2);
                float bx = s_bias[ncol], by = s_bias[ncol + 1];
                float2 v0 = make_float2(acc[mi][ni][0] + bx, acc[mi][ni][1] + by);
                float2 v1 = make_float2(acc[mi][ni][2] + bx, acc[mi][ni][3] + by);
                *reinterpret_cast<float2*>(g_xp + (size_t)mrow * G4_ + ncol) = v0;
                *reinterpret_cast<float2*>(g_xp + (size_t)(mrow + 8) * G4_ + ncol) = v1;
            }
        }
        __syncthreads();
    }
}

// ===========================================================================
// Kernel 2: persistent LSTM scan — EXACT R12 config (frozen optimum, 96% of
// the fp32 FMA floor; R7/R13 proved more W regs regress). tanh.approx.
// 128 CTAs x 2 batch rows x 512 threads.
// ===========================================================================
__device__ __forceinline__ float tanh_fast(float x) {
    float y;
    asm("tanh.approx.f32 %0, %1;" : "=f"(y) : "f"(x));
    return y;
}
__device__ __forceinline__ float sigmoid_fast(float x) {
    return fmaf(tanh_fast(0.5f * x), 0.5f, 0.5f);
}

#define LS_SMEM ((256 + 2048 + 32768) * 4)   // sh_h + gbuf + Wst = 140288 B

__global__ __launch_bounds__(512, 1) void lstm_kernel(const float* __restrict__ Whh)
{
    extern __shared__ float smem_l[];
    float*  sh_h = smem_l;                 // [2][128]
    float*  gbuf = smem_l + 256;           // 2048 gate partials
    float4* Wst  = reinterpret_cast<float4*>(smem_l + 256 + 2048); // [32 k4][256 r]

    const int tid = threadIdx.x;
    const int hb  = tid >> 8;
    const int r   = tid & 255;
    const int b0  = blockIdx.x * 2;

    const ulonglong2* Wll = reinterpret_cast<const ulonglong2*>(Whh);
    const float4*     W4  = reinterpret_cast<const float4*>(Whh);

    unsigned long long wr[32];
    #pragma unroll
    for (int i = 0; i < 16; i++) {
        ulonglong2 v = Wll[(size_t)r * 32 + (hb << 4) + i];
        wr[2 * i]     = v.x;
        wr[2 * i + 1] = v.y;
    }
    #pragma unroll
    for (int i = 0; i < 16; i++) {
        int idx = tid + (i << 9);
        int k4 = idx >> 8, rr = idx & 255;
        Wst[k4 * 256 + rr] = W4[(size_t)(256 + rr) * 32 + k4];
    }

    if (tid < 256) sh_h[tid] = 0.0f;
    float c_reg = 0.0f;

    const bool cb = (tid < 256);
    const int  b  = (tid >> 7) & 1;
    const int  j  = tid & 127;

    const float* my_xp = g_xp + (size_t)(b0 + b) * T_ * G4_;
    float*       my_hs = g_hs + (size_t)(b0 + b) * T_ * H_;

    const char* sh0 = (const char*)sh_h + (hb << 8);
    const float4* Wmy = Wst + (hb << 4) * 256 + r;

    __syncthreads();

    for (int t = 0; t < T_; t++) {
        float xpi = 0.f, xpf = 0.f, xpg = 0.f, xpo = 0.f;
        if (cb) {
            const float* xpt = my_xp + (size_t)t * G4_;
            xpi = __ldg(xpt + j);
            xpf = __ldg(xpt + 128 + j);
            xpg = __ldg(xpt + 256 + j);
            xpo = __ldg(xpt + 384 + j);
        }

        unsigned long long aa0 = 0ull, aa1 = 0ull;
        unsigned long long qq0 = 0ull, qq1 = 0ull;
        #pragma unroll
        for (int kk = 0; kk < 16; kk++) {
            ulonglong2 h0 = *reinterpret_cast<const ulonglong2*>(sh0 + kk * 16);
            ulonglong2 h1 = *reinterpret_cast<const ulonglong2*>(sh0 + 512 + kk * 16);
            ulonglong2 ws = *reinterpret_cast<const ulonglong2*>(Wmy + kk * 256);
            aa0 = fma2(wr[2 * kk],     h0.x, aa0);
            aa0 = fma2(wr[2 * kk + 1], h0.y, aa0);
            aa1 = fma2(wr[2 * kk],     h1.x, aa1);
            aa1 = fma2(wr[2 * kk + 1], h1.y, aa1);
            qq0 = fma2(ws.x, h0.x, qq0);
            qq0 = fma2(ws.y, h0.y, qq0);
            qq1 = fma2(ws.x, h1.x, qq1);
            qq1 = fma2(ws.y, h1.y, qq1);
        }
        gbuf[(hb << 9) + r]               = sum2(aa0);
        gbuf[(hb << 9) + 256 + r]         = sum2(aa1);
        gbuf[1024 + (hb << 9) + r]        = sum2(qq0);
        gbuf[1024 + (hb << 9) + 256 + r]  = sum2(qq1);
        __syncthreads();

        if (cb) {
            float gi = gbuf[(b << 8) + j]              + gbuf[512 + (b << 8) + j]              + xpi;
            float gf = gbuf[(b << 8) + 128 + j]        + gbuf[512 + (b << 8) + 128 + j]        + xpf;
            float gg = gbuf[1024 + (b << 8) + j]       + gbuf[1536 + (b << 8) + j]             + xpg;
            float go = gbuf[1024 + (b << 8) + 128 + j] + gbuf[1536 + (b << 8) + 128 + j]       + xpo;

            float si = sigmoid_fast(gi);
            float sf = sigmoid_fast(gf);
            float so = sigmoid_fast(go);
            float tg = tanh_fast(gg);

            c_reg = fmaf(sf, c_reg, si * tg);
            float hn = so * tanh_fast(c_reg);

            sh_h[(b << 7) + j]        = hn;
            my_hs[(size_t)t * H_ + j] = hn;
        }
        __syncthreads();
    }
}

// ===========================================================================
// Kernel 3: attention pooling — fused single-pass online softmax (R14 config,
// best measured 93.9us). One CTA per batch row; 16 tiles of 128 timesteps.
// ===========================================================================
#define AT_TILE 128

__global__ __launch_bounds__(256) void attn_kernel(float* __restrict__ out)
{
    __shared__ float h_sm[AT_TILE * H_];   // 64 KB tile
    __shared__ float s_sc[AT_TILE];
    __shared__ float red[8];
    __shared__ float redA[256];
    __shared__ float redL[256];

    const int b    = blockIdx.x;
    const int tid  = threadIdx.x;
    const int lane = tid & 31;
    const int warp = tid >> 5;
    const int j    = tid & 127;
    const int tp   = tid >> 7;

    const float4* hs4 = reinterpret_cast<const float4*>(g_hs + (size_t)b * T_ * H_);
    float4* h_sm4 = reinterpret_cast<float4*>(h_sm);

    const float4 hl = hs4[(size_t)(T_ - 1) * 32 + lane];

    float m_run = -3.0e38f;
    float accj  = 0.0f;
    float lpart = 0.0f;

    for (int tile = 0; tile < T_ / AT_TILE; tile++) {
        const int t0 = tile * AT_TILE;

        #pragma unroll
        for (int i = 0; i < 16; i++) {
            int idx = tid + i * 256;
            h_sm4[idx] = hs4[(size_t)(t0 + (idx >> 5)) * 32 + (idx & 31)];
        }
        __syncthreads();

        float lmax = -3.0e38f;
        #pragma unroll
        for (int i = 0; i < 16; i++) {
            int t = warp + 8 * i;
            float4 hv = h_sm4[t * 32 + lane];
            float d = fmaf(hv.x, hl.x, fmaf(hv.y, hl.y, fmaf(hv.z, hl.z, hv.w * hl.w)));
            #pragma unroll
            for (int s = 16; s > 0; s >>= 1) d += __shfl_xor_sync(0xffffffffu, d, s);
            if (lane == 0) s_sc[t] = d;
            lmax = fmaxf(lmax, d);
        }
        if (lane == 0) red[warp] = lmax;
        __syncthreads();

        float tmax = red[0];
        #pragma unroll
        for (int w = 1; w < 8; w++) tmax = fmaxf(tmax, red[w]);
        const float new_m = fmaxf(m_run, tmax);
        const float fac   = __expf(m_run - new_m);
        accj  *= fac;
        lpart *= fac;
        m_run  = new_m;

        if (tid < 128) s_sc[tid] = __expf(s_sc[tid] - new_m);
        __syncthreads();

        #pragma unroll 4
        for (int i = 0; i < AT_TILE / 2; i++) {
            int t = tp + 2 * i;
            float w = s_sc[t];
            accj = fmaf(w, h_sm[t * H_ + j], accj);
            lpart += w;
        }
        __syncthreads();
    }

    redA[tid] = accj;
    redL[tid] = lpart;
    __syncthreads();
    if (tid < 128) {
        float a = redA[tid] + redA[tid + 128];
        float l = redL[tid] + redL[tid + 128];
        out[b * H_ + tid] = a * __fdividef(1.0f, l);
    }
}

// ===========================================================================
extern "C" void kernel_launch(void* const* d_in, const int* in_sizes, int n_in,
                              void* d_out, int out_size)
{
    (void)in_sizes; (void)n_in; (void)out_size;
    const float* x   = (const float*)d_in[0];
    const float* Wih = (const float*)d_in[1];
    const float* Whh = (const float*)d_in[2];
    const float* bih = (const float*)d_in[3];
    const float* bhh = (const float*)d_in[4];
    float* out = (float*)d_out;

    cudaFuncSetAttribute(xproj_mma_kernel, cudaFuncAttributeMaxDynamicSharedMemorySize, XS_SIZE);
    cudaFuncSetAttribute(lstm_kernel,      cudaFuncAttributeMaxDynamicSharedMemorySize, LS_SMEM);

    wsplit_kernel<<<64, 256>>>(Wih);
    xproj_mma_kernel<<<M_ / 128, 256, XS_SIZE>>>(x, bih, bhh);
    lstm_kernel<<<B_ / 2, 512, LS_SMEM>>>(Whh);
    attn_kernel<<<B_, 256>>>(out);
}